// round 2
// baseline (speedup 1.0000x reference)
#include <cuda_runtime.h>
#include <cstdint>
#include <cstddef>

// Problem sizes (fixed by the reference): B=32, T=64 -> BT=2048
// audio [BT,128], video [BT,48,512], W_audio[512,128], b_audio[512],
// W_video[512,512], b_video[512], W_v[48,512], W_g[48,512], W_h[1,48]
#define BT_TOTAL 2048
#define SV 516   // padded smem row stride (floats) -> conflict-free A-frag LDS

// ---------------- device scratch (no allocation allowed) ----------------
__device__ float2 g_Wvf[64 * 64 * 32];   // W_video tf32, pre-shuffled into mma B-frag order
__device__ float2 g_Wvvf[6 * 64 * 32];   // W_v     tf32, pre-shuffled into mma B-frag order
__device__ float  g_inter[BT_TOTAL * 48];

// ---------------- helpers ----------------
__device__ __forceinline__ uint32_t rna_u(float x) {
    uint32_t u;
    asm("cvt.rna.tf32.f32 %0, %1;" : "=r"(u) : "f"(x));
    return u;
}
__device__ __forceinline__ float rna_f(float x) { return __uint_as_float(rna_u(x)); }

__device__ __forceinline__ void mma_tf32(float& d0, float& d1, float& d2, float& d3,
                                         uint32_t a0, uint32_t a1, uint32_t a2, uint32_t a3,
                                         uint32_t b0, uint32_t b1) {
    asm volatile(
        "mma.sync.aligned.m16n8k8.row.col.f32.tf32.tf32.f32 "
        "{%0,%1,%2,%3}, {%4,%5,%6,%7}, {%8,%9}, {%0,%1,%2,%3};\n"
        : "+f"(d0), "+f"(d1), "+f"(d2), "+f"(d3)
        : "r"(a0), "r"(a1), "r"(a2), "r"(a3), "r"(b0), "r"(b1));
}

// ---------------- kernel 1: prepare tf32-rounded, frag-ordered weights ----------------
// B-frag layout for mma.m16n8k8 (row.col):  b0 = B[k0 + l%4][n0 + l/4], b1 = B[k0+4+l%4][n0+l/4]
// For v = V @ W^T :  B[k][h] = W[h][k]  ->  b0 = W[n0 + l/4][k0 + l%4], b1 = same row, k+4.
__global__ void prep_kernel(const float* __restrict__ Wvid, const float* __restrict__ Wv) {
    int idx = blockIdx.x * 256 + threadIdx.x;
    if (idx < 64 * 64 * 32) {
        int lane = idx & 31;
        int tile = idx >> 5;          // h8*64 + ks
        int h8 = tile >> 6, ks = tile & 63;
        int row = h8 * 8 + (lane >> 2);
        int col = ks * 8 + (lane & 3);
        g_Wvf[idx] = make_float2(rna_f(Wvid[row * 512 + col]),
                                 rna_f(Wvid[row * 512 + col + 4]));
    } else {
        int j = idx - 64 * 64 * 32;
        if (j < 6 * 64 * 32) {
            int lane = j & 31;
            int tile = j >> 5;        // m8*64 + ks
            int m8 = tile >> 6, ks = tile & 63;
            int row = m8 * 8 + (lane >> 2);
            int col = ks * 8 + (lane & 3);
            g_Wvvf[j] = make_float2(rna_f(Wv[row * 512 + col]),
                                    rna_f(Wv[row * 512 + col + 4]));
        }
    }
}

// ---------------- kernel 2: audio path -> inter[bt][48] ----------------
__global__ __launch_bounds__(256) void audio_kernel(const float* __restrict__ audio,
                                                    const float* __restrict__ W_audio,
                                                    const float* __restrict__ b_audio,
                                                    const float* __restrict__ W_g) {
    __shared__ float audio_s[16 * 128];
    __shared__ float a_s[16 * 512];
    int t = threadIdx.x;
    int cb = blockIdx.x;  // 16 bt per CTA

    const float* ag = audio + (size_t)cb * 16 * 128;
#pragma unroll
    for (int i = 0; i < 8; i++) audio_s[t + i * 256] = ag[t + i * 256];
    __syncthreads();

    // a[r][h] = relu(audio[r] . W_audio[h] + b_audio[h])
#pragma unroll 2
    for (int j = 0; j < 32; j++) {
        int idx = t + j * 256;
        int r = idx >> 9, h = idx & 511;
        const float4* wr = (const float4*)(W_audio + (size_t)h * 128);
        const float4* ar = (const float4*)(audio_s + r * 128);
        float s = 0.f;
#pragma unroll
        for (int kk = 0; kk < 32; kk++) {
            float4 wv = wr[kk];
            float4 av = ar[kk];
            s += wv.x * av.x + wv.y * av.y + wv.z * av.z + wv.w * av.w;
        }
        s += b_audio[h];
        a_s[idx] = s > 0.f ? s : 0.f;
    }
    __syncthreads();

    // inter[r][m] = a[r] . W_g[m]
#pragma unroll
    for (int j = 0; j < 3; j++) {
        int idx = t + j * 256;          // 768 = r*48 + m
        int r = idx / 48, m = idx % 48;
        const float4* as4 = (const float4*)(a_s + r * 512);
        const float4* wg = (const float4*)(W_g + (size_t)m * 512);
        float s = 0.f;
#pragma unroll 8
        for (int kk = 0; kk < 128; kk++) {
            float4 a4 = as4[kk];
            float4 w4 = wg[kk];
            s += a4.x * w4.x + a4.y * w4.y + a4.z * w4.z + a4.w * w4.w;
        }
        g_inter[(size_t)cb * 768 + idx] = s;
    }
}

// ---------------- kernel 3: fused main kernel, one CTA per bt ----------------
// smem: Vs[48*516] | vs[48*516] | bvs[512] | inter_s[48] | wh_s[48] | zpart[96] | red[2] | alpha_s[48]
#define SMEM_FLOATS (48 * SV * 2 + 512 + 48 + 48 + 96 + 2 + 48)

__global__ __launch_bounds__(256, 1) void main_kernel(const float* __restrict__ video,
                                                      const float* __restrict__ b_video,
                                                      const float* __restrict__ W_h,
                                                      float* __restrict__ out) {
    extern __shared__ float sm[];
    float* Vs = sm;
    float* vs = Vs + 48 * SV;
    float* bvs = vs + 48 * SV;
    float* inter_s = bvs + 512;
    float* wh_s = inter_s + 48;
    float* zpart = wh_s + 48;
    float* red = zpart + 96;
    float* alpha_s = red + 2;

    int t = threadIdx.x;
    int bt = blockIdx.x;
    int lane = t & 31, w = t >> 5;
    int qid = lane >> 2, tq = lane & 3;

    // ---- phase 0: stage V (tf32-rounded) + small vectors ----
    const float4* Vg = (const float4*)(video + (size_t)bt * 48 * 512);
#pragma unroll
    for (int i = 0; i < 24; i++) {
        int e4 = t + i * 256;
        float4 x = Vg[e4];
        int e = e4 * 4;
        int n = e >> 9, k = e & 511;
        float4 y = make_float4(rna_f(x.x), rna_f(x.y), rna_f(x.z), rna_f(x.w));
        *(float4*)&Vs[n * SV + k] = y;
    }
    bvs[t] = b_video[t];
    bvs[t + 256] = b_video[t + 256];
    if (t < 48) {
        inter_s[t] = g_inter[(size_t)bt * 48 + t];
        wh_s[t] = W_h[t];
    }
    __syncthreads();

    // ---- phase 1: v = relu(V @ W_video^T + b)  (M=48, N=512, K=512) ----
    // warp w owns h in [w*64, w*64+64): 3 m16 tiles x 8 n8 tiles
    float acc[3][8][4];
#pragma unroll
    for (int mt = 0; mt < 3; mt++)
#pragma unroll
        for (int nt = 0; nt < 8; nt++)
#pragma unroll
            for (int r = 0; r < 4; r++) acc[mt][nt][r] = 0.f;

    const float* A0 = Vs + qid * SV + tq;
    const float2* Bp = g_Wvf + (size_t)(w * 8) * 64 * 32 + lane;

    float2 bb[2][8];
#pragma unroll
    for (int nt = 0; nt < 8; nt++) bb[0][nt] = Bp[(size_t)(nt * 64) * 32];

#pragma unroll 2
    for (int ks = 0; ks < 64; ks++) {
        int cur = ks & 1;
        if (ks < 63) {
#pragma unroll
            for (int nt = 0; nt < 8; nt++)
                bb[cur ^ 1][nt] = Bp[(size_t)(nt * 64 + ks + 1) * 32];
        }
        int k0 = ks * 8;
        uint32_t a[3][4];
#pragma unroll
        for (int mt = 0; mt < 3; mt++) {
            const float* Ap = A0 + mt * 16 * SV;
            a[mt][0] = __float_as_uint(Ap[k0]);
            a[mt][1] = __float_as_uint(Ap[8 * SV + k0]);
            a[mt][2] = __float_as_uint(Ap[k0 + 4]);
            a[mt][3] = __float_as_uint(Ap[8 * SV + k0 + 4]);
        }
#pragma unroll
        for (int nt = 0; nt < 8; nt++) {
            uint32_t b0 = __float_as_uint(bb[cur][nt].x);
            uint32_t b1 = __float_as_uint(bb[cur][nt].y);
#pragma unroll
            for (int mt = 0; mt < 3; mt++)
                mma_tf32(acc[mt][nt][0], acc[mt][nt][1], acc[mt][nt][2], acc[mt][nt][3],
                         a[mt][0], a[mt][1], a[mt][2], a[mt][3], b0, b1);
        }
    }

    // epilogue: relu(+bias), round to tf32, store v to smem
#pragma unroll
    for (int mt = 0; mt < 3; mt++) {
#pragma unroll
        for (int nt = 0; nt < 8; nt++) {
            int r0 = mt * 16 + qid;
            int h0 = w * 64 + nt * 8 + tq * 2;
            float bv0 = bvs[h0], bv1 = bvs[h0 + 1];
            float x0 = acc[mt][nt][0] + bv0; x0 = x0 > 0.f ? x0 : 0.f;
            float x1 = acc[mt][nt][1] + bv1; x1 = x1 > 0.f ? x1 : 0.f;
            float x2 = acc[mt][nt][2] + bv0; x2 = x2 > 0.f ? x2 : 0.f;
            float x3 = acc[mt][nt][3] + bv1; x3 = x3 > 0.f ? x3 : 0.f;
            *(float2*)&vs[r0 * SV + h0] = make_float2(rna_f(x0), rna_f(x1));
            *(float2*)&vs[(r0 + 8) * SV + h0] = make_float2(rna_f(x2), rna_f(x3));
        }
    }
    __syncthreads();

    // ---- phase 2: content = v @ W_v^T (+inter), tanh, z partials ----
    // 6 warps, each owns (m16 tile) x (3 of 6 n8 tiles) exclusively -> no reduction
    if (w < 6) {
        int mt = w >> 1, nh = w & 1;
        float cacc[3][4];
#pragma unroll
        for (int j = 0; j < 3; j++)
#pragma unroll
            for (int r = 0; r < 4; r++) cacc[j][r] = 0.f;

        const float* Ap0 = vs + (mt * 16 + qid) * SV + tq;
#pragma unroll 2
        for (int ks = 0; ks < 64; ks++) {
            int k0 = ks * 8;
            uint32_t a0 = __float_as_uint(Ap0[k0]);
            uint32_t a1 = __float_as_uint(Ap0[8 * SV + k0]);
            uint32_t a2 = __float_as_uint(Ap0[k0 + 4]);
            uint32_t a3 = __float_as_uint(Ap0[8 * SV + k0 + 4]);
#pragma unroll
            for (int j = 0; j < 3; j++) {
                float2 b = g_Wvvf[(size_t)((nh * 3 + j) * 64 + ks) * 32 + lane];
                mma_tf32(cacc[j][0], cacc[j][1], cacc[j][2], cacc[j][3],
                         a0, a1, a2, a3, __float_as_uint(b.x), __float_as_uint(b.y));
            }
        }

        int n0 = mt * 16 + qid, n1 = n0 + 8;
        float i0 = inter_s[n0], i1 = inter_s[n1];
        float p0 = 0.f, p1 = 0.f;
#pragma unroll
        for (int j = 0; j < 3; j++) {
            int m0 = (nh * 3 + j) * 8 + tq * 2;
            float wh0 = wh_s[m0], wh1 = wh_s[m0 + 1];
            p0 += tanhf(cacc[j][0] + i0) * wh0 + tanhf(cacc[j][1] + i0) * wh1;
            p1 += tanhf(cacc[j][2] + i1) * wh0 + tanhf(cacc[j][3] + i1) * wh1;
        }
        p0 += __shfl_xor_sync(0xffffffffu, p0, 1);
        p0 += __shfl_xor_sync(0xffffffffu, p0, 2);
        p1 += __shfl_xor_sync(0xffffffffu, p1, 1);
        p1 += __shfl_xor_sync(0xffffffffu, p1, 2);
        if (tq == 0) {
            zpart[n0 * 2 + nh] = p0;
            zpart[n1 * 2 + nh] = p1;
        }
    }
    __syncthreads();

    // ---- phase 3: softmax over 48 ----
    if (t < 48) alpha_s[t] = zpart[t * 2] + zpart[t * 2 + 1];
    __syncthreads();
    if (t == 0) {
        float m = -1e30f;
        for (int n = 0; n < 48; n++) m = fmaxf(m, alpha_s[n]);
        red[0] = m;
    }
    __syncthreads();
    if (t < 48) alpha_s[t] = expf(alpha_s[t] - red[0]);
    __syncthreads();
    if (t == 0) {
        float s = 0.f;
        for (int n = 0; n < 48; n++) s += alpha_s[n];
        red[1] = 1.0f / s;
    }
    __syncthreads();

    // ---- phase 4: c[k] = sum_n alpha[n] * V[n][k] ----
    float inv = red[1];
#pragma unroll
    for (int rep = 0; rep < 2; rep++) {
        int k = t + rep * 256;
        float s = 0.f;
#pragma unroll
        for (int n = 0; n < 48; n++) s += alpha_s[n] * Vs[n * SV + k];
        out[(size_t)bt * 512 + k] = s * inv;
    }
}

// ---------------- launch ----------------
extern "C" void kernel_launch(void* const* d_in, const int* in_sizes, int n_in,
                              void* d_out, int out_size) {
    const float* audio   = (const float*)d_in[0];
    const float* video   = (const float*)d_in[1];
    const float* W_audio = (const float*)d_in[2];
    const float* b_audio = (const float*)d_in[3];
    const float* W_video = (const float*)d_in[4];
    const float* b_video = (const float*)d_in[5];
    const float* W_v     = (const float*)d_in[6];
    const float* W_g     = (const float*)d_in[7];
    const float* W_h     = (const float*)d_in[8];
    float* out = (float*)d_out;

    (void)in_sizes; (void)n_in; (void)out_size;

    const int smem_bytes = SMEM_FLOATS * 4;
    cudaFuncSetAttribute(main_kernel, cudaFuncAttributeMaxDynamicSharedMemorySize, smem_bytes);

    prep_kernel<<<560, 256>>>(W_video, W_v);
    audio_kernel<<<BT_TOTAL / 16, 256>>>(audio, W_audio, b_audio, W_g);
    main_kernel<<<BT_TOTAL, 256, smem_bytes>>>(video, b_video, W_h, out);
}

// round 3
// speedup vs baseline: 1.0003x; 1.0003x over previous
#include <cuda_runtime.h>
#include <cstdint>
#include <cstddef>

// Problem sizes (fixed by the reference): B=32, T=64 -> BT=2048
// audio [BT,128], video [BT,48,512], W_audio[512,128], b_audio[512],
// W_video[512,512], b_video[512], W_v[48,512], W_g[48,512], W_h[1,48]
#define BT_TOTAL 2048
#define SV 516   // padded smem row stride (floats) -> conflict-free A-frag LDS

// ---------------- device scratch (no allocation allowed) ----------------
__device__ float2 g_Wvf[64 * 64 * 32];   // W_video tf32, pre-shuffled into mma B-frag order
__device__ float2 g_Wvvf[6 * 64 * 32];   // W_v     tf32, pre-shuffled into mma B-frag order
__device__ float  g_inter[BT_TOTAL * 48];

// ---------------- helpers ----------------
__device__ __forceinline__ uint32_t rna_u(float x) {
    uint32_t u;
    asm("cvt.rna.tf32.f32 %0, %1;" : "=r"(u) : "f"(x));
    return u;
}
__device__ __forceinline__ float rna_f(float x) { return __uint_as_float(rna_u(x)); }

__device__ __forceinline__ void mma_tf32(float& d0, float& d1, float& d2, float& d3,
                                         uint32_t a0, uint32_t a1, uint32_t a2, uint32_t a3,
                                         uint32_t b0, uint32_t b1) {
    asm volatile(
        "mma.sync.aligned.m16n8k8.row.col.f32.tf32.tf32.f32 "
        "{%0,%1,%2,%3}, {%4,%5,%6,%7}, {%8,%9}, {%0,%1,%2,%3};\n"
        : "+f"(d0), "+f"(d1), "+f"(d2), "+f"(d3)
        : "r"(a0), "r"(a1), "r"(a2), "r"(a3), "r"(b0), "r"(b1));
}

// ---------------- kernel 1: prepare tf32-rounded, frag-ordered weights ----------------
// B-frag layout for mma.m16n8k8 (row.col):  b0 = B[k0 + l%4][n0 + l/4], b1 = B[k0+4+l%4][n0+l/4]
// For v = V @ W^T :  B[k][h] = W[h][k]  ->  b0 = W[n0 + l/4][k0 + l%4], b1 = same row, k+4.
__global__ void prep_kernel(const float* __restrict__ Wvid, const float* __restrict__ Wv) {
    int idx = blockIdx.x * 256 + threadIdx.x;
    if (idx < 64 * 64 * 32) {
        int lane = idx & 31;
        int tile = idx >> 5;          // h8*64 + ks
        int h8 = tile >> 6, ks = tile & 63;
        int row = h8 * 8 + (lane >> 2);
        int col = ks * 8 + (lane & 3);
        g_Wvf[idx] = make_float2(rna_f(Wvid[row * 512 + col]),
                                 rna_f(Wvid[row * 512 + col + 4]));
    } else {
        int j = idx - 64 * 64 * 32;
        if (j < 6 * 64 * 32) {
            int lane = j & 31;
            int tile = j >> 5;        // m8*64 + ks
            int m8 = tile >> 6, ks = tile & 63;
            int row = m8 * 8 + (lane >> 2);
            int col = ks * 8 + (lane & 3);
            g_Wvvf[j] = make_float2(rna_f(Wv[row * 512 + col]),
                                    rna_f(Wv[row * 512 + col + 4]));
        }
    }
}

// ---------------- kernel 2: audio path -> inter[bt][48] ----------------
__global__ __launch_bounds__(256) void audio_kernel(const float* __restrict__ audio,
                                                    const float* __restrict__ W_audio,
                                                    const float* __restrict__ b_audio,
                                                    const float* __restrict__ W_g) {
    __shared__ float audio_s[16 * 128];
    __shared__ float a_s[16 * 512];
    int t = threadIdx.x;
    int cb = blockIdx.x;  // 16 bt per CTA

    const float* ag = audio + (size_t)cb * 16 * 128;
#pragma unroll
    for (int i = 0; i < 8; i++) audio_s[t + i * 256] = ag[t + i * 256];
    __syncthreads();

    // a[r][h] = relu(audio[r] . W_audio[h] + b_audio[h])
#pragma unroll 2
    for (int j = 0; j < 32; j++) {
        int idx = t + j * 256;
        int r = idx >> 9, h = idx & 511;
        const float4* wr = (const float4*)(W_audio + (size_t)h * 128);
        const float4* ar = (const float4*)(audio_s + r * 128);
        float s = 0.f;
#pragma unroll
        for (int kk = 0; kk < 32; kk++) {
            float4 wv = wr[kk];
            float4 av = ar[kk];
            s += wv.x * av.x + wv.y * av.y + wv.z * av.z + wv.w * av.w;
        }
        s += b_audio[h];
        a_s[idx] = s > 0.f ? s : 0.f;
    }
    __syncthreads();

    // inter[r][m] = a[r] . W_g[m]
#pragma unroll
    for (int j = 0; j < 3; j++) {
        int idx = t + j * 256;          // 768 = r*48 + m
        int r = idx / 48, m = idx % 48;
        const float4* as4 = (const float4*)(a_s + r * 512);
        const float4* wg = (const float4*)(W_g + (size_t)m * 512);
        float s = 0.f;
#pragma unroll 8
        for (int kk = 0; kk < 128; kk++) {
            float4 a4 = as4[kk];
            float4 w4 = wg[kk];
            s += a4.x * w4.x + a4.y * w4.y + a4.z * w4.z + a4.w * w4.w;
        }
        g_inter[(size_t)cb * 768 + idx] = s;
    }
}

// ---------------- kernel 3: fused main kernel, one CTA per bt ----------------
// smem: Vs[48*516] | vs[48*516] | bvs[512] | inter_s[48] | wh_s[48] | zpart[96] | red[2] | alpha_s[48]
#define SMEM_FLOATS (48 * SV * 2 + 512 + 48 + 48 + 96 + 2 + 48)

__global__ __launch_bounds__(256, 1) void main_kernel(const float* __restrict__ video,
                                                      const float* __restrict__ b_video,
                                                      const float* __restrict__ W_h,
                                                      float* __restrict__ out) {
    extern __shared__ float sm[];
    float* Vs = sm;
    float* vs = Vs + 48 * SV;
    float* bvs = vs + 48 * SV;
    float* inter_s = bvs + 512;
    float* wh_s = inter_s + 48;
    float* zpart = wh_s + 48;
    float* red = zpart + 96;
    float* alpha_s = red + 2;

    int t = threadIdx.x;
    int bt = blockIdx.x;
    int lane = t & 31, w = t >> 5;
    int qid = lane >> 2, tq = lane & 3;

    // ---- phase 0: stage V (tf32-rounded) + small vectors ----
    const float4* Vg = (const float4*)(video + (size_t)bt * 48 * 512);
#pragma unroll
    for (int i = 0; i < 24; i++) {
        int e4 = t + i * 256;
        float4 x = Vg[e4];
        int e = e4 * 4;
        int n = e >> 9, k = e & 511;
        float4 y = make_float4(rna_f(x.x), rna_f(x.y), rna_f(x.z), rna_f(x.w));
        *(float4*)&Vs[n * SV + k] = y;
    }
    bvs[t] = b_video[t];
    bvs[t + 256] = b_video[t + 256];
    if (t < 48) {
        inter_s[t] = g_inter[(size_t)bt * 48 + t];
        wh_s[t] = W_h[t];
    }
    __syncthreads();

    // ---- phase 1: v = relu(V @ W_video^T + b)  (M=48, N=512, K=512) ----
    // warp w owns h in [w*64, w*64+64): 3 m16 tiles x 8 n8 tiles
    float acc[3][8][4];
#pragma unroll
    for (int mt = 0; mt < 3; mt++)
#pragma unroll
        for (int nt = 0; nt < 8; nt++)
#pragma unroll
            for (int r = 0; r < 4; r++) acc[mt][nt][r] = 0.f;

    const float* A0 = Vs + qid * SV + tq;
    const float2* Bp = g_Wvf + (size_t)(w * 8) * 64 * 32 + lane;

    float2 bb[2][8];
#pragma unroll
    for (int nt = 0; nt < 8; nt++) bb[0][nt] = Bp[(size_t)(nt * 64) * 32];

#pragma unroll 2
    for (int ks = 0; ks < 64; ks++) {
        int cur = ks & 1;
        if (ks < 63) {
#pragma unroll
            for (int nt = 0; nt < 8; nt++)
                bb[cur ^ 1][nt] = Bp[(size_t)(nt * 64 + ks + 1) * 32];
        }
        int k0 = ks * 8;
        uint32_t a[3][4];
#pragma unroll
        for (int mt = 0; mt < 3; mt++) {
            const float* Ap = A0 + mt * 16 * SV;
            a[mt][0] = __float_as_uint(Ap[k0]);
            a[mt][1] = __float_as_uint(Ap[8 * SV + k0]);
            a[mt][2] = __float_as_uint(Ap[k0 + 4]);
            a[mt][3] = __float_as_uint(Ap[8 * SV + k0 + 4]);
        }
#pragma unroll
        for (int nt = 0; nt < 8; nt++) {
            uint32_t b0 = __float_as_uint(bb[cur][nt].x);
            uint32_t b1 = __float_as_uint(bb[cur][nt].y);
#pragma unroll
            for (int mt = 0; mt < 3; mt++)
                mma_tf32(acc[mt][nt][0], acc[mt][nt][1], acc[mt][nt][2], acc[mt][nt][3],
                         a[mt][0], a[mt][1], a[mt][2], a[mt][3], b0, b1);
        }
    }

    // epilogue: relu(+bias), round to tf32, store v to smem
#pragma unroll
    for (int mt = 0; mt < 3; mt++) {
#pragma unroll
        for (int nt = 0; nt < 8; nt++) {
            int r0 = mt * 16 + qid;
            int h0 = w * 64 + nt * 8 + tq * 2;
            float bv0 = bvs[h0], bv1 = bvs[h0 + 1];
            float x0 = acc[mt][nt][0] + bv0; x0 = x0 > 0.f ? x0 : 0.f;
            float x1 = acc[mt][nt][1] + bv1; x1 = x1 > 0.f ? x1 : 0.f;
            float x2 = acc[mt][nt][2] + bv0; x2 = x2 > 0.f ? x2 : 0.f;
            float x3 = acc[mt][nt][3] + bv1; x3 = x3 > 0.f ? x3 : 0.f;
            *(float2*)&vs[r0 * SV + h0] = make_float2(rna_f(x0), rna_f(x1));
            *(float2*)&vs[(r0 + 8) * SV + h0] = make_float2(rna_f(x2), rna_f(x3));
        }
    }
    __syncthreads();

    // ---- phase 2: content = v @ W_v^T (+inter), tanh, z partials ----
    // 6 warps, each owns (m16 tile) x (3 of 6 n8 tiles) exclusively -> no reduction
    if (w < 6) {
        int mt = w >> 1, nh = w & 1;
        float cacc[3][4];
#pragma unroll
        for (int j = 0; j < 3; j++)
#pragma unroll
            for (int r = 0; r < 4; r++) cacc[j][r] = 0.f;

        const float* Ap0 = vs + (mt * 16 + qid) * SV + tq;
#pragma unroll 2
        for (int ks = 0; ks < 64; ks++) {
            int k0 = ks * 8;
            uint32_t a0 = __float_as_uint(Ap0[k0]);
            uint32_t a1 = __float_as_uint(Ap0[8 * SV + k0]);
            uint32_t a2 = __float_as_uint(Ap0[k0 + 4]);
            uint32_t a3 = __float_as_uint(Ap0[8 * SV + k0 + 4]);
#pragma unroll
            for (int j = 0; j < 3; j++) {
                float2 b = g_Wvvf[(size_t)((nh * 3 + j) * 64 + ks) * 32 + lane];
                mma_tf32(cacc[j][0], cacc[j][1], cacc[j][2], cacc[j][3],
                         a0, a1, a2, a3, __float_as_uint(b.x), __float_as_uint(b.y));
            }
        }

        int n0 = mt * 16 + qid, n1 = n0 + 8;
        float i0 = inter_s[n0], i1 = inter_s[n1];
        float p0 = 0.f, p1 = 0.f;
#pragma unroll
        for (int j = 0; j < 3; j++) {
            int m0 = (nh * 3 + j) * 8 + tq * 2;
            float wh0 = wh_s[m0], wh1 = wh_s[m0 + 1];
            p0 += tanhf(cacc[j][0] + i0) * wh0 + tanhf(cacc[j][1] + i0) * wh1;
            p1 += tanhf(cacc[j][2] + i1) * wh0 + tanhf(cacc[j][3] + i1) * wh1;
        }
        p0 += __shfl_xor_sync(0xffffffffu, p0, 1);
        p0 += __shfl_xor_sync(0xffffffffu, p0, 2);
        p1 += __shfl_xor_sync(0xffffffffu, p1, 1);
        p1 += __shfl_xor_sync(0xffffffffu, p1, 2);
        if (tq == 0) {
            zpart[n0 * 2 + nh] = p0;
            zpart[n1 * 2 + nh] = p1;
        }
    }
    __syncthreads();

    // ---- phase 3: softmax over 48 ----
    if (t < 48) alpha_s[t] = zpart[t * 2] + zpart[t * 2 + 1];
    __syncthreads();
    if (t == 0) {
        float m = -1e30f;
        for (int n = 0; n < 48; n++) m = fmaxf(m, alpha_s[n]);
        red[0] = m;
    }
    __syncthreads();
    if (t < 48) alpha_s[t] = expf(alpha_s[t] - red[0]);
    __syncthreads();
    if (t == 0) {
        float s = 0.f;
        for (int n = 0; n < 48; n++) s += alpha_s[n];
        red[1] = 1.0f / s;
    }
    __syncthreads();

    // ---- phase 4: c[k] = sum_n alpha[n] * V[n][k] ----
    float inv = red[1];
#pragma unroll
    for (int rep = 0; rep < 2; rep++) {
        int k = t + rep * 256;
        float s = 0.f;
#pragma unroll
        for (int n = 0; n < 48; n++) s += alpha_s[n] * Vs[n * SV + k];
        out[(size_t)bt * 512 + k] = s * inv;
    }
}

// ---------------- launch ----------------
extern "C" void kernel_launch(void* const* d_in, const int* in_sizes, int n_in,
                              void* d_out, int out_size) {
    const float* audio   = (const float*)d_in[0];
    const float* video   = (const float*)d_in[1];
    const float* W_audio = (const float*)d_in[2];
    const float* b_audio = (const float*)d_in[3];
    const float* W_video = (const float*)d_in[4];
    const float* b_video = (const float*)d_in[5];
    const float* W_v     = (const float*)d_in[6];
    const float* W_g     = (const float*)d_in[7];
    const float* W_h     = (const float*)d_in[8];
    float* out = (float*)d_out;

    (void)in_sizes; (void)n_in; (void)out_size;

    const int smem_bytes = SMEM_FLOATS * 4;
    cudaFuncSetAttribute(main_kernel, cudaFuncAttributeMaxDynamicSharedMemorySize, smem_bytes);

    prep_kernel<<<560, 256>>>(W_video, W_v);
    audio_kernel<<<BT_TOTAL / 16, 256>>>(audio, W_audio, b_audio, W_g);
    main_kernel<<<BT_TOTAL, 256, smem_bytes>>>(video, b_video, W_h, out);
}

// round 4
// speedup vs baseline: 1.0670x; 1.0667x over previous
#include <cuda_runtime.h>
#include <cstdint>
#include <cstddef>

// B=32, T=64 -> BT=2048. audio [BT,128], video [BT,48,512], W_audio[512,128],
// b_audio[512], W_video[512,512], b_video[512], W_v[48,512], W_g[48,512], W_h[1,48]
#define BT_TOTAL 2048
#define SV   516            // vs row stride (floats): conflict-free A-frag LDS
#define KT   32             // A k-tile
#define STA  36             // A tile row stride (floats): 36*4B rows, 16B aligned, conflict-free
#define TILE_F (96 * STA)   // floats per A tile stage

// ---------------- device scratch ----------------
__device__ float2 g_Wvf[64 * 64 * 32];   // W_video tf32, mma B-frag order
__device__ float2 g_Wvvf[6 * 64 * 32];   // W_v     tf32, mma B-frag order
__device__ float  g_inter[BT_TOTAL * 48];

// ---------------- helpers ----------------
__device__ __forceinline__ uint32_t rna_u(float x) {
    uint32_t u; asm("cvt.rna.tf32.f32 %0, %1;" : "=r"(u) : "f"(x)); return u;
}
__device__ __forceinline__ float rna_f(float x) { return __uint_as_float(rna_u(x)); }

__device__ __forceinline__ void mma_tf32(float& d0, float& d1, float& d2, float& d3,
                                         uint32_t a0, uint32_t a1, uint32_t a2, uint32_t a3,
                                         uint32_t b0, uint32_t b1) {
    asm volatile(
        "mma.sync.aligned.m16n8k8.row.col.f32.tf32.tf32.f32 "
        "{%0,%1,%2,%3}, {%4,%5,%6,%7}, {%8,%9}, {%0,%1,%2,%3};\n"
        : "+f"(d0), "+f"(d1), "+f"(d2), "+f"(d3)
        : "r"(a0), "r"(a1), "r"(a2), "r"(a3), "r"(b0), "r"(b1));
}

__device__ __forceinline__ void cp_async16(uint32_t saddr, const float* gaddr) {
    asm volatile("cp.async.ca.shared.global [%0], [%1], 16;" :: "r"(saddr), "l"(gaddr));
}
#define CP_COMMIT() asm volatile("cp.async.commit_group;")
#define CP_WAIT(n)  asm volatile("cp.async.wait_group %0;" :: "n"(n))

// ---------------- kernel 1: frag-ordered tf32 weights ----------------
// b0 = W[n0 + l/4][k0 + l%4], b1 = same row, k0+4  (for X @ W^T with mma row.col)
__global__ void prep_kernel(const float* __restrict__ Wvid, const float* __restrict__ Wv) {
    int idx = blockIdx.x * 256 + threadIdx.x;
    if (idx < 64 * 64 * 32) {
        int lane = idx & 31, tile = idx >> 5;
        int h8 = tile >> 6, ks = tile & 63;
        int row = h8 * 8 + (lane >> 2), col = ks * 8 + (lane & 3);
        g_Wvf[idx] = make_float2(rna_f(Wvid[row * 512 + col]),
                                 rna_f(Wvid[row * 512 + col + 4]));
    } else {
        int j = idx - 64 * 64 * 32;
        if (j < 6 * 64 * 32) {
            int lane = j & 31, tile = j >> 5;
            int m8 = tile >> 6, ks = tile & 63;
            int row = m8 * 8 + (lane >> 2), col = ks * 8 + (lane & 3);
            g_Wvvf[j] = make_float2(rna_f(Wv[row * 512 + col]),
                                    rna_f(Wv[row * 512 + col + 4]));
        }
    }
}

// ---------------- kernel 2: audio path -> inter[bt][48] ----------------
__global__ __launch_bounds__(256) void audio_kernel(const float* __restrict__ audio,
                                                    const float* __restrict__ W_audio,
                                                    const float* __restrict__ b_audio,
                                                    const float* __restrict__ W_g) {
    __shared__ float audio_s[16 * 128];
    __shared__ float a_s[16 * 512];
    int t = threadIdx.x;
    int cb = blockIdx.x;

    const float* ag = audio + (size_t)cb * 16 * 128;
#pragma unroll
    for (int i = 0; i < 8; i++) audio_s[t + i * 256] = ag[t + i * 256];
    __syncthreads();

#pragma unroll 2
    for (int j = 0; j < 32; j++) {
        int idx = t + j * 256;
        int r = idx >> 9, h = idx & 511;
        const float4* wr = (const float4*)(W_audio + (size_t)h * 128);
        const float4* ar = (const float4*)(audio_s + r * 128);
        float s = 0.f;
#pragma unroll
        for (int kk = 0; kk < 32; kk++) {
            float4 wv = wr[kk], av = ar[kk];
            s += wv.x * av.x + wv.y * av.y + wv.z * av.z + wv.w * av.w;
        }
        s += b_audio[h];
        a_s[idx] = s > 0.f ? s : 0.f;
    }
    __syncthreads();

#pragma unroll
    for (int j = 0; j < 3; j++) {
        int idx = t + j * 256;
        int r = idx / 48, m = idx % 48;
        const float4* as4 = (const float4*)(a_s + r * 512);
        const float4* wg = (const float4*)(W_g + (size_t)m * 512);
        float s = 0.f;
#pragma unroll 8
        for (int kk = 0; kk < 128; kk++) {
            float4 a4 = as4[kk], w4 = wg[kk];
            s += a4.x * w4.x + a4.y * w4.y + a4.z * w4.z + a4.w * w4.w;
        }
        g_inter[(size_t)cb * 768 + idx] = s;
    }
}

// ---------------- kernel 3: fused main, 2 bt per CTA, 512 threads ----------------
// smem: vs[96*516] | Atile[2*96*36] | bvs[512] | inter_s[96] | wh_s[48] |
//       zpart[2*96] | red[4] | alpha_s[96]
#define SMEM_FLOATS (96 * SV + 2 * TILE_F + 512 + 96 + 48 + 192 + 4 + 96)

__device__ __forceinline__ void issue_tile(float* tile_s, const float* gsrc, int t) {
    // 96 rows x 32 floats = 768 float4 chunks; gsrc row stride 512
    {
        int row = t >> 3, c4 = t & 7;
        cp_async16((uint32_t)__cvta_generic_to_shared(tile_s + row * STA + c4 * 4),
                   gsrc + (size_t)row * 512 + c4 * 4);
    }
    if (t < 256) {
        int idx = t + 512;
        int row = idx >> 3, c4 = idx & 7;
        cp_async16((uint32_t)__cvta_generic_to_shared(tile_s + row * STA + c4 * 4),
                   gsrc + (size_t)row * 512 + c4 * 4);
    }
}

__global__ __launch_bounds__(512, 1) void main_kernel(const float* __restrict__ video,
                                                      const float* __restrict__ b_video,
                                                      const float* __restrict__ W_h,
                                                      float* __restrict__ out) {
    extern __shared__ float sm[];
    float* vs      = sm;
    float* tiles   = vs + 96 * SV;
    float* bvs     = tiles + 2 * TILE_F;
    float* inter_s = bvs + 512;
    float* wh_s    = inter_s + 96;
    float* zpart   = wh_s + 48;          // [2][96]
    float* red     = zpart + 192;        // [2][2]
    float* alpha_s = red + 4;            // [2][48]

    int t = threadIdx.x;
    int blk = blockIdx.x;                // handles bt = 2*blk, 2*blk+1
    int lane = t & 31, w = t >> 5;       // 16 warps
    int qid = lane >> 2, tq = lane & 3;

    const float* Vg = video + (size_t)blk * 96 * 512;   // 96 contiguous rows

    // ---- phase 0: start A pipeline + small vectors ----
    issue_tile(tiles, Vg, t);            CP_COMMIT();
    issue_tile(tiles + TILE_F, Vg + KT, t); CP_COMMIT();
    bvs[t] = b_video[t & 511];
    if (t < 96) inter_s[t] = g_inter[(size_t)blk * 96 + t];
    if (t < 48) wh_s[t] = W_h[t];

    // ---- phase 1: v = relu(V @ W_video^T + b)  (M=96, N=512, K=512) ----
    // warp w owns h in [w*32, w*32+32): 4 n8 tiles; all 6 m16 tiles
    float acc[6][4][4];
#pragma unroll
    for (int mt = 0; mt < 6; mt++)
#pragma unroll
        for (int j = 0; j < 4; j++)
#pragma unroll
            for (int r = 0; r < 4; r++) acc[mt][j][r] = 0.f;

    const float2* Bp = g_Wvf + (size_t)(w * 4) * 64 * 32 + lane;
    float2 bb[2][4];
#pragma unroll
    for (int j = 0; j < 4; j++) bb[0][j] = Bp[(size_t)(j * 64) * 32];

    for (int tile = 0; tile < 16; ++tile) {
        if (tile == 15) { CP_WAIT(0); } else { CP_WAIT(1); }
        __syncthreads();
        const float* Ab = tiles + (tile & 1) * TILE_F + qid * STA + tq;
#pragma unroll
        for (int kk = 0; kk < 4; kk++) {
            int ks = tile * 4 + kk;
            int cur = kk & 1;
            if (ks < 63) {
#pragma unroll
                for (int j = 0; j < 4; j++)
                    bb[cur ^ 1][j] = Bp[(size_t)(j * 64 + ks + 1) * 32];
            }
            int k0 = kk * 8;
#pragma unroll
            for (int mt = 0; mt < 6; mt++) {
                const float* Ap = Ab + mt * 16 * STA;
                uint32_t a0 = __float_as_uint(Ap[k0]);
                uint32_t a1 = __float_as_uint(Ap[8 * STA + k0]);
                uint32_t a2 = __float_as_uint(Ap[k0 + 4]);
                uint32_t a3 = __float_as_uint(Ap[8 * STA + k0 + 4]);
#pragma unroll
                for (int j = 0; j < 4; j++)
                    mma_tf32(acc[mt][j][0], acc[mt][j][1], acc[mt][j][2], acc[mt][j][3],
                             a0, a1, a2, a3,
                             __float_as_uint(bb[cur][j].x), __float_as_uint(bb[cur][j].y));
            }
        }
        __syncthreads();
        if (tile + 2 < 16) {
            issue_tile(tiles + (tile & 1) * TILE_F, Vg + (size_t)(tile + 2) * KT, t);
            CP_COMMIT();
        }
    }

    // epilogue: relu(+bias), tf32-round, store v to smem
#pragma unroll
    for (int mt = 0; mt < 6; mt++) {
#pragma unroll
        for (int j = 0; j < 4; j++) {
            int r0 = mt * 16 + qid;
            int h0 = w * 32 + j * 8 + tq * 2;
            float bv0 = bvs[h0], bv1 = bvs[h0 + 1];
            float x0 = acc[mt][j][0] + bv0; x0 = x0 > 0.f ? x0 : 0.f;
            float x1 = acc[mt][j][1] + bv1; x1 = x1 > 0.f ? x1 : 0.f;
            float x2 = acc[mt][j][2] + bv0; x2 = x2 > 0.f ? x2 : 0.f;
            float x3 = acc[mt][j][3] + bv1; x3 = x3 > 0.f ? x3 : 0.f;
            *(float2*)&vs[r0 * SV + h0]       = make_float2(rna_f(x0), rna_f(x1));
            *(float2*)&vs[(r0 + 8) * SV + h0] = make_float2(rna_f(x2), rna_f(x3));
        }
    }
    __syncthreads();

    // ---- phase 2: content = v @ W_v^T (+inter), tanh, z partials ----
    // 12 warps: 6 per bt; each owns m16 tile x 3 n8 tiles exclusively
    if (w < 12) {
        int btl = w / 6, wl = w % 6;
        int mt = wl >> 1, nh = wl & 1;
        float cacc[3][4];
#pragma unroll
        for (int j = 0; j < 3; j++)
#pragma unroll
            for (int r = 0; r < 4; r++) cacc[j][r] = 0.f;

        const float* Ap0 = vs + (btl * 48 + mt * 16 + qid) * SV + tq;
#pragma unroll 2
        for (int ks = 0; ks < 64; ks++) {
            int k0 = ks * 8;
            uint32_t a0 = __float_as_uint(Ap0[k0]);
            uint32_t a1 = __float_as_uint(Ap0[8 * SV + k0]);
            uint32_t a2 = __float_as_uint(Ap0[k0 + 4]);
            uint32_t a3 = __float_as_uint(Ap0[8 * SV + k0 + 4]);
#pragma unroll
            for (int j = 0; j < 3; j++) {
                float2 b = g_Wvvf[(size_t)((nh * 3 + j) * 64 + ks) * 32 + lane];
                mma_tf32(cacc[j][0], cacc[j][1], cacc[j][2], cacc[j][3],
                         a0, a1, a2, a3, __float_as_uint(b.x), __float_as_uint(b.y));
            }
        }

        int n0 = mt * 16 + qid, n1 = n0 + 8;
        float i0 = inter_s[btl * 48 + n0], i1 = inter_s[btl * 48 + n1];
        float p0 = 0.f, p1 = 0.f;
#pragma unroll
        for (int j = 0; j < 3; j++) {
            int m0 = (nh * 3 + j) * 8 + tq * 2;
            float wh0 = wh_s[m0], wh1 = wh_s[m0 + 1];
            p0 += tanhf(cacc[j][0] + i0) * wh0 + tanhf(cacc[j][1] + i0) * wh1;
            p1 += tanhf(cacc[j][2] + i1) * wh0 + tanhf(cacc[j][3] + i1) * wh1;
        }
        p0 += __shfl_xor_sync(0xffffffffu, p0, 1);
        p0 += __shfl_xor_sync(0xffffffffu, p0, 2);
        p1 += __shfl_xor_sync(0xffffffffu, p1, 1);
        p1 += __shfl_xor_sync(0xffffffffu, p1, 2);
        if (tq == 0) {
            zpart[btl * 96 + n0 * 2 + nh] = p0;
            zpart[btl * 96 + n1 * 2 + nh] = p1;
        }
    }
    __syncthreads();

    // ---- phase 3: softmax over 48, per bt ----
    if (t < 96) {
        int btl = t / 48, n = t % 48;
        alpha_s[t] = zpart[btl * 96 + n * 2] + zpart[btl * 96 + n * 2 + 1];
    }
    __syncthreads();
    if (t == 0 || t == 256) {
        int btl = t >> 8;
        float m = -1e30f;
        for (int n = 0; n < 48; n++) m = fmaxf(m, alpha_s[btl * 48 + n]);
        red[btl * 2] = m;
    }
    __syncthreads();
    if (t < 96) alpha_s[t] = expf(alpha_s[t] - red[(t / 48) * 2]);
    __syncthreads();
    if (t == 0 || t == 256) {
        int btl = t >> 8;
        float s = 0.f;
        for (int n = 0; n < 48; n++) s += alpha_s[btl * 48 + n];
        red[btl * 2 + 1] = 1.0f / s;
    }
    __syncthreads();

    // ---- phase 4: c[k] = sum_n alpha[n] * V[n][k], exact V from global ----
    {
        int btl = t >> 8, k = t & 255;
        const float* Vrow = Vg + (size_t)btl * 48 * 512;
        float inv = red[btl * 2 + 1];
        const float* al = alpha_s + btl * 48;
        float s0 = 0.f, s1 = 0.f;
#pragma unroll 8
        for (int n = 0; n < 48; n++) {
            float a = al[n];
            s0 += a * Vrow[(size_t)n * 512 + k];
            s1 += a * Vrow[(size_t)n * 512 + k + 256];
        }
        float* ob = out + (size_t)(blk * 2 + btl) * 512;
        ob[k] = s0 * inv;
        ob[k + 256] = s1 * inv;
    }
}

// ---------------- launch ----------------
extern "C" void kernel_launch(void* const* d_in, const int* in_sizes, int n_in,
                              void* d_out, int out_size) {
    const float* audio   = (const float*)d_in[0];
    const float* video   = (const float*)d_in[1];
    const float* W_audio = (const float*)d_in[2];
    const float* b_audio = (const float*)d_in[3];
    const float* W_video = (const float*)d_in[4];
    const float* b_video = (const float*)d_in[5];
    const float* W_v     = (const float*)d_in[6];
    const float* W_g     = (const float*)d_in[7];
    const float* W_h     = (const float*)d_in[8];
    float* out = (float*)d_out;

    (void)in_sizes; (void)n_in; (void)out_size;

    const int smem_bytes = SMEM_FLOATS * 4;   // ~229.6 KB
    cudaFuncSetAttribute(main_kernel, cudaFuncAttributeMaxDynamicSharedMemorySize, smem_bytes);

    prep_kernel<<<560, 256>>>(W_video, W_v);
    audio_kernel<<<BT_TOTAL / 16, 256>>>(audio, W_audio, b_audio, W_g);
    main_kernel<<<BT_TOTAL / 2, 512, smem_bytes>>>(video, b_video, W_h, out);
}

// round 6
// speedup vs baseline: 1.5748x; 1.4758x over previous
#include <cuda_runtime.h>
#include <cuda_fp16.h>
#include <cstdint>
#include <cstddef>

// B=32, T=64 -> BT=2048. audio [BT,128], video [BT,48,512], W_audio[512,128],
// b_audio[512], W_video[512,512], b_video[512], W_v[48,512], W_g[48,512], W_h[1,48]
#define BT_TOTAL 2048
#define STAF 40              // A-tile row stride in floats (160B): LDS.64 conflict-free
#define TILE_F (96 * STAF)   // floats per A stage
#define SVH 520              // vs row stride in halfs (1040B): LDS.32 conflict-free

// ---------------- device scratch ----------------
__device__ uint2 g_Wvf[64 * 32 * 32];   // W_video fp16 B-frags: [h8][k16][lane] (512KB)
__device__ uint2 g_Wvvf[6 * 32 * 32];   // W_v     fp16 B-frags: [m8][k16][lane] (48KB)
__device__ float g_inter[BT_TOTAL * 48];

// ---------------- helpers ----------------
__device__ __forceinline__ uint32_t packh2(float lo, float hi) {
    __half2 h = __floats2half2_rn(lo, hi);
    return *(uint32_t*)&h;
}

__device__ __forceinline__ void mma_f16(float& d0, float& d1, float& d2, float& d3,
                                        uint32_t a0, uint32_t a1, uint32_t a2, uint32_t a3,
                                        uint32_t b0, uint32_t b1) {
    asm volatile(
        "mma.sync.aligned.m16n8k16.row.col.f32.f16.f16.f32 "
        "{%0,%1,%2,%3}, {%4,%5,%6,%7}, {%8,%9}, {%0,%1,%2,%3};\n"
        : "+f"(d0), "+f"(d1), "+f"(d2), "+f"(d3)
        : "r"(a0), "r"(a1), "r"(a2), "r"(a3), "r"(b0), "r"(b1));
}

__device__ __forceinline__ void cp_async16(uint32_t saddr, const float* gaddr) {
    asm volatile("cp.async.ca.shared.global [%0], [%1], 16;" :: "r"(saddr), "l"(gaddr));
}
#define CP_COMMIT() asm volatile("cp.async.commit_group;")
#define CP_WAIT(n)  asm volatile("cp.async.wait_group %0;" :: "n"(n))

// ---------------- kernel 1: fp16 frag-ordered weights ----------------
// m16n8k16 row.col B-frag: b0 = {B[k0+(l%4)*2][n0+l/4], B[k0+(l%4)*2+1][n0+l/4]},
// b1 = same with k+8.  For X @ W^T: B[k][n] = W[n][k].
__global__ void prep_kernel(const float* __restrict__ Wvid, const float* __restrict__ Wv) {
    int idx = blockIdx.x * 256 + threadIdx.x;
    if (idx < 64 * 32 * 32) {
        int lane = idx & 31, tile = idx >> 5;
        int h8 = tile >> 5, ks = tile & 31;
        int row = h8 * 8 + (lane >> 2);
        int col = ks * 16 + (lane & 3) * 2;
        const float* W = Wvid + (size_t)row * 512 + col;
        g_Wvf[idx] = make_uint2(packh2(W[0], W[1]), packh2(W[8], W[9]));
    } else {
        int j = idx - 64 * 32 * 32;
        if (j < 6 * 32 * 32) {
            int lane = j & 31, tile = j >> 5;
            int m8 = tile >> 5, ks = tile & 31;
            int row = m8 * 8 + (lane >> 2);
            int col = ks * 16 + (lane & 3) * 2;
            const float* W = Wv + (size_t)row * 512 + col;
            g_Wvvf[j] = make_uint2(packh2(W[0], W[1]), packh2(W[8], W[9]));
        }
    }
}

// ---------------- kernel 2: audio path -> inter[bt][48] ----------------
__global__ __launch_bounds__(256) void audio_kernel(const float* __restrict__ audio,
                                                    const float* __restrict__ W_audio,
                                                    const float* __restrict__ b_audio,
                                                    const float* __restrict__ W_g) {
    __shared__ float audio_s[16 * 128];
    __shared__ float a_s[16 * 512];
    int t = threadIdx.x;
    int cb = blockIdx.x;

    const float* ag = audio + (size_t)cb * 16 * 128;
#pragma unroll
    for (int i = 0; i < 8; i++) audio_s[t + i * 256] = ag[t + i * 256];
    __syncthreads();

#pragma unroll 2
    for (int j = 0; j < 32; j++) {
        int idx = t + j * 256;
        int r = idx >> 9, h = idx & 511;
        const float4* wr = (const float4*)(W_audio + (size_t)h * 128);
        const float4* ar = (const float4*)(audio_s + r * 128);
        float s = 0.f;
#pragma unroll
        for (int kk = 0; kk < 32; kk++) {
            float4 wv = wr[kk], av = ar[kk];
            s += wv.x * av.x + wv.y * av.y + wv.z * av.z + wv.w * av.w;
        }
        s += b_audio[h];
        a_s[idx] = s > 0.f ? s : 0.f;
    }
    __syncthreads();

#pragma unroll
    for (int j = 0; j < 3; j++) {
        int idx = t + j * 256;
        int r = idx / 48, m = idx % 48;
        const float4* as4 = (const float4*)(a_s + r * 512);
        const float4* wg = (const float4*)(W_g + (size_t)m * 512);
        float s = 0.f;
#pragma unroll 8
        for (int kk = 0; kk < 128; kk++) {
            float4 a4 = as4[kk], w4 = wg[kk];
            s += a4.x * w4.x + a4.y * w4.y + a4.z * w4.z + a4.w * w4.w;
        }
        g_inter[(size_t)cb * 768 + idx] = s;
    }
}

// ---------------- kernel 3: fused main, 2 bt per CTA, 512 threads ----------------
// smem bytes: vs(half) 96*520*2=99840 @0 | Atiles(f32) 2*3840*4=30720 @99840 |
// bvs 2048 @130560 | inter 384 @132608 | wh 192 @132992 | zpart 768 @133184 |
// red 16 @133952 | alpha 384 @133968  -> total 134352
#define OF_TILES 99840
#define OF_BVS   130560
#define OF_INTER 132608
#define OF_WH    132992
#define OF_ZP    133184
#define OF_RED   133952
#define OF_AL    133968
#define SMEM_BYTES 134368

__device__ __forceinline__ void issue_tile(uint32_t tbase, const float* gsrc, int t) {
    // 96 rows x 32 floats = 768 16B chunks; gmem row stride 512 floats
    {
        int row = t >> 3, c4 = t & 7;
        cp_async16(tbase + (uint32_t)(row * 160 + c4 * 16),
                   gsrc + (size_t)row * 512 + c4 * 4);
    }
    if (t < 256) {
        int g = t + 512;
        int row = g >> 3, c4 = g & 7;
        cp_async16(tbase + (uint32_t)(row * 160 + c4 * 16),
                   gsrc + (size_t)row * 512 + c4 * 4);
    }
}

__global__ __launch_bounds__(512, 1) void main_kernel(const float* __restrict__ video,
                                                      const float* __restrict__ b_video,
                                                      const float* __restrict__ W_h,
                                                      float* __restrict__ out) {
    extern __shared__ char smc[];
    uint32_t sbase = (uint32_t)__cvta_generic_to_shared(smc);
    __half* vs     = (__half*)smc;
    float* tiles   = (float*)(smc + OF_TILES);
    float* bvs     = (float*)(smc + OF_BVS);
    float* inter_s = (float*)(smc + OF_INTER);
    float* wh_s    = (float*)(smc + OF_WH);
    float* zpart   = (float*)(smc + OF_ZP);
    float* red     = (float*)(smc + OF_RED);
    float* alpha_s = (float*)(smc + OF_AL);

    int t = threadIdx.x;
    int blk = blockIdx.x;                 // bt = 2*blk, 2*blk+1
    int lane = t & 31, w = t >> 5;        // 16 warps
    int qid = lane >> 2, tq = lane & 3;

    const float* Vg = video + (size_t)blk * 96 * 512;

    // ---- phase 0: start A pipeline + small vectors ----
    issue_tile(sbase + OF_TILES, Vg, t);                      CP_COMMIT();
    issue_tile(sbase + OF_TILES + TILE_F * 4, Vg + 32, t);    CP_COMMIT();
    bvs[t] = b_video[t];
    if (t < 96) inter_s[t] = g_inter[(size_t)blk * 96 + t];
    if (t < 48) wh_s[t] = W_h[t];

    // ---- phase 1: v = relu(V @ W_video^T + b)  (M=96, N=512, K=512), fp16 mma ----
    // warp w owns h in [w*32, w*32+32): 4 n8 tiles; all 6 m16 tiles
    float acc[6][4][4];
#pragma unroll
    for (int mt = 0; mt < 6; mt++)
#pragma unroll
        for (int j = 0; j < 4; j++)
#pragma unroll
            for (int r = 0; r < 4; r++) acc[mt][j][r] = 0.f;

    const uint2* Bp = g_Wvf + (size_t)(w * 4) * 32 * 32 + lane;
    uint2 bb[2][4];
#pragma unroll
    for (int j = 0; j < 4; j++) bb[0][j] = Bp[(size_t)(j * 32) * 32];

    for (int tile = 0; tile < 16; ++tile) {
        if (tile == 15) { CP_WAIT(0); } else { CP_WAIT(1); }
        __syncthreads();
        const float* Ab = tiles + (tile & 1) * TILE_F;
#pragma unroll
        for (int kk = 0; kk < 2; kk++) {
            int kg = tile * 2 + kk;       // k16 step 0..31
            int cur = kg & 1;
            if (kg < 31) {
#pragma unroll
                for (int j = 0; j < 4; j++)
                    bb[cur ^ 1][j] = Bp[(size_t)(j * 32 + kg + 1) * 32];
            }
            int k0 = kk * 16;
#pragma unroll
            for (int mt = 0; mt < 6; mt++) {
                const float* Ap = Ab + (mt * 16 + qid) * STAF + k0 + tq * 2;
                float2 v00 = *(const float2*)Ap;               // row qid,   k..k+1
                float2 v01 = *(const float2*)(Ap + 8);         // row qid,   k+8..k+9
                float2 v10 = *(const float2*)(Ap + 8 * STAF);  // row qid+8, k..k+1
                float2 v11 = *(const float2*)(Ap + 8 * STAF + 8);
                uint32_t a0 = packh2(v00.x, v00.y);
                uint32_t a1 = packh2(v10.x, v10.y);
                uint32_t a2 = packh2(v01.x, v01.y);
                uint32_t a3 = packh2(v11.x, v11.y);
#pragma unroll
                for (int j = 0; j < 4; j++)
                    mma_f16(acc[mt][j][0], acc[mt][j][1], acc[mt][j][2], acc[mt][j][3],
                            a0, a1, a2, a3, bb[cur][j].x, bb[cur][j].y);
            }
        }
        __syncthreads();
        if (tile + 2 < 16) {
            issue_tile(sbase + OF_TILES + (tile & 1) * TILE_F * 4,
                       Vg + (size_t)(tile + 2) * 32, t);
            CP_COMMIT();
        }
    }

    // epilogue: relu(+bias), pack fp16 pairs, store v to smem
#pragma unroll
    for (int mt = 0; mt < 6; mt++) {
#pragma unroll
        for (int j = 0; j < 4; j++) {
            int r0 = mt * 16 + qid;
            int h0 = w * 32 + j * 8 + tq * 2;
            float bv0 = bvs[h0], bv1 = bvs[h0 + 1];
            float x0 = acc[mt][j][0] + bv0; x0 = x0 > 0.f ? x0 : 0.f;
            float x1 = acc[mt][j][1] + bv1; x1 = x1 > 0.f ? x1 : 0.f;
            float x2 = acc[mt][j][2] + bv0; x2 = x2 > 0.f ? x2 : 0.f;
            float x3 = acc[mt][j][3] + bv1; x3 = x3 > 0.f ? x3 : 0.f;
            *(uint32_t*)&vs[r0 * SVH + h0]       = packh2(x0, x1);
            *(uint32_t*)&vs[(r0 + 8) * SVH + h0] = packh2(x2, x3);
        }
    }
    __syncthreads();

    // ---- phase 2: content = v @ W_v^T (+inter), tanh, z partials (fp16 mma) ----
    // 12 warps: 6 per bt; warp owns m16 tile x 3 n8 tiles exclusively
    if (w < 12) {
        int btl = w / 6, wl = w % 6;
        int mt = wl >> 1, nh = wl & 1;
        float cacc[3][4];
#pragma unroll
        for (int j = 0; j < 3; j++)
#pragma unroll
            for (int r = 0; r < 4; r++) cacc[j][r] = 0.f;

        const __half* Ap0 = vs + (btl * 48 + mt * 16 + qid) * SVH + tq * 2;
#pragma unroll 4
        for (int ks = 0; ks < 32; ks++) {
            int k0 = ks * 16;
            uint32_t a0 = *(const uint32_t*)(Ap0 + k0);
            uint32_t a1 = *(const uint32_t*)(Ap0 + 8 * SVH + k0);
            uint32_t a2 = *(const uint32_t*)(Ap0 + k0 + 8);
            uint32_t a3 = *(const uint32_t*)(Ap0 + 8 * SVH + k0 + 8);
#pragma unroll
            for (int j = 0; j < 3; j++) {
                uint2 b = g_Wvvf[(size_t)((nh * 3 + j) * 32 + ks) * 32 + lane];
                mma_f16(cacc[j][0], cacc[j][1], cacc[j][2], cacc[j][3],
                        a0, a1, a2, a3, b.x, b.y);
            }
        }

        int n0 = mt * 16 + qid, n1 = n0 + 8;
        float i0 = inter_s[btl * 48 + n0], i1 = inter_s[btl * 48 + n1];
        float p0 = 0.f, p1 = 0.f;
#pragma unroll
        for (int j = 0; j < 3; j++) {
            int m0i = (nh * 3 + j) * 8 + tq * 2;
            float wh0 = wh_s[m0i], wh1 = wh_s[m0i + 1];
            p0 += tanhf(cacc[j][0] + i0) * wh0 + tanhf(cacc[j][1] + i0) * wh1;
            p1 += tanhf(cacc[j][2] + i1) * wh0 + tanhf(cacc[j][3] + i1) * wh1;
        }
        p0 += __shfl_xor_sync(0xffffffffu, p0, 1);
        p0 += __shfl_xor_sync(0xffffffffu, p0, 2);
        p1 += __shfl_xor_sync(0xffffffffu, p1, 1);
        p1 += __shfl_xor_sync(0xffffffffu, p1, 2);
        if (tq == 0) {
            zpart[btl * 96 + n0 * 2 + nh] = p0;
            zpart[btl * 96 + n1 * 2 + nh] = p1;
        }
    }
    __syncthreads();

    // ---- phase 3: softmax over 48, per bt ----
    if (t < 96) {
        int btl = t / 48, n = t % 48;
        alpha_s[t] = zpart[btl * 96 + n * 2] + zpart[btl * 96 + n * 2 + 1];
    }
    __syncthreads();
    if (t == 0 || t == 256) {
        int btl = t >> 8;
        float m = -1e30f;
        for (int n = 0; n < 48; n++) m = fmaxf(m, alpha_s[btl * 48 + n]);
        red[btl * 2] = m;
    }
    __syncthreads();
    if (t < 96) alpha_s[t] = expf(alpha_s[t] - red[(t / 48) * 2]);
    __syncthreads();
    if (t == 0 || t == 256) {
        int btl = t >> 8;
        float s = 0.f;
        for (int n = 0; n < 48; n++) s += alpha_s[btl * 48 + n];
        red[btl * 2 + 1] = 1.0f / s;
    }
    __syncthreads();

    // ---- phase 4: c[k] = sum_n alpha[n] * V[n][k], exact V from global ----
    {
        int btl = t >> 8, k = t & 255;
        const float* Vrow = Vg + (size_t)btl * 48 * 512;
        float inv = red[btl * 2 + 1];
        const float* al = alpha_s + btl * 48;
        float s0 = 0.f, s1 = 0.f;
#pragma unroll 8
        for (int n = 0; n < 48; n++) {
            float a = al[n];
            s0 += a * Vrow[(size_t)n * 512 + k];
            s1 += a * Vrow[(size_t)n * 512 + k + 256];
        }
        float* ob = out + (size_t)(blk * 2 + btl) * 512;
        ob[k] = s0 * inv;
        ob[k + 256] = s1 * inv;
    }
}

// ---------------- launch ----------------
extern "C" void kernel_launch(void* const* d_in, const int* in_sizes, int n_in,
                              void* d_out, int out_size) {
    const float* audio   = (const float*)d_in[0];
    const float* video   = (const float*)d_in[1];
    const float* W_audio = (const float*)d_in[2];
    const float* b_audio = (const float*)d_in[3];
    const float* W_video = (const float*)d_in[4];
    const float* b_video = (const float*)d_in[5];
    const float* W_v     = (const float*)d_in[6];
    const float* W_g     = (const float*)d_in[7];
    const float* W_h     = (const float*)d_in[8];
    float* out = (float*)d_out;

    (void)in_sizes; (void)n_in; (void)out_size;

    cudaFuncSetAttribute(main_kernel, cudaFuncAttributeMaxDynamicSharedMemorySize, SMEM_BYTES);

    prep_kernel<<<280, 256>>>(W_video, W_v);
    audio_kernel<<<BT_TOTAL / 16, 256>>>(audio, W_audio, b_audio, W_g);
    main_kernel<<<BT_TOTAL / 2, 512, SMEM_BYTES>>>(video, b_video, W_h, out);
}

// round 7
// speedup vs baseline: 1.6798x; 1.0667x over previous
#include <cuda_runtime.h>
#include <cuda_fp16.h>
#include <cstdint>
#include <cstddef>

// B=32, T=64 -> BT=2048. audio [BT,128], video [BT,48,512], W_audio[512,128],
// b_audio[512], W_video[512,512], b_video[512], W_v[48,512], W_g[48,512], W_h[1,48]
#define BT_TOTAL 2048
#define SVH 520               // vs row stride (halfs); 1040B -> LDSM conflict-free
#define KT 64                 // A k-tile (8 tiles over K=512)
#define STH 72                // fp16 tile row stride (halfs); 144B -> LDSM conflict-free

// ---------------- device scratch ----------------
__device__ uint2 g_Wvf[64 * 32 * 32];   // W_video fp16 B-frags: [h8][k16][lane] (512KB)
__device__ uint2 g_Wvvf[6 * 32 * 32];   // W_v     fp16 B-frags: [m8][k16][lane] (48KB)
__device__ float g_inter[BT_TOTAL * 48];

// ---------------- helpers ----------------
__device__ __forceinline__ uint32_t packh2(float lo, float hi) {
    __half2 h = __floats2half2_rn(lo, hi);
    return *(uint32_t*)&h;
}

__device__ __forceinline__ void mma_f16(float& d0, float& d1, float& d2, float& d3,
                                        uint32_t a0, uint32_t a1, uint32_t a2, uint32_t a3,
                                        uint32_t b0, uint32_t b1) {
    asm volatile(
        "mma.sync.aligned.m16n8k16.row.col.f32.f16.f16.f32 "
        "{%0,%1,%2,%3}, {%4,%5,%6,%7}, {%8,%9}, {%0,%1,%2,%3};\n"
        : "+f"(d0), "+f"(d1), "+f"(d2), "+f"(d3)
        : "r"(a0), "r"(a1), "r"(a2), "r"(a3), "r"(b0), "r"(b1));
}

__device__ __forceinline__ void ldsm_x4(uint32_t& a0, uint32_t& a1, uint32_t& a2, uint32_t& a3,
                                        uint32_t saddr) {
    asm volatile("ldmatrix.sync.aligned.m8n8.x4.shared.b16 {%0,%1,%2,%3}, [%4];"
                 : "=r"(a0), "=r"(a1), "=r"(a2), "=r"(a3) : "r"(saddr));
}

__device__ __forceinline__ void cp_async16(uint32_t saddr, const float* gaddr) {
    asm volatile("cp.async.ca.shared.global [%0], [%1], 16;" :: "r"(saddr), "l"(gaddr));
}
#define CP_COMMIT() asm volatile("cp.async.commit_group;")
#define CP_WAIT(n)  asm volatile("cp.async.wait_group %0;" :: "n"(n))

// ---------------- kernel 1: fp16 frag-ordered weights ----------------
__global__ void prep_kernel(const float* __restrict__ Wvid, const float* __restrict__ Wv) {
    int idx = blockIdx.x * 256 + threadIdx.x;
    if (idx < 64 * 32 * 32) {
        int lane = idx & 31, tile = idx >> 5;
        int h8 = tile >> 5, ks = tile & 31;
        int row = h8 * 8 + (lane >> 2);
        int col = ks * 16 + (lane & 3) * 2;
        const float* W = Wvid + (size_t)row * 512 + col;
        g_Wvf[idx] = make_uint2(packh2(W[0], W[1]), packh2(W[8], W[9]));
    } else {
        int j = idx - 64 * 32 * 32;
        if (j < 6 * 32 * 32) {
            int lane = j & 31, tile = j >> 5;
            int m8 = tile >> 5, ks = tile & 31;
            int row = m8 * 8 + (lane >> 2);
            int col = ks * 16 + (lane & 3) * 2;
            const float* W = Wv + (size_t)row * 512 + col;
            g_Wvvf[j] = make_uint2(packh2(W[0], W[1]), packh2(W[8], W[9]));
        }
    }
}

// ---------------- kernel 2: audio path -> inter[bt][48] ----------------
__global__ __launch_bounds__(256) void audio_kernel(const float* __restrict__ audio,
                                                    const float* __restrict__ W_audio,
                                                    const float* __restrict__ b_audio,
                                                    const float* __restrict__ W_g) {
    __shared__ float audio_s[16 * 128];
    __shared__ float a_s[16 * 512];
    int t = threadIdx.x;
    int cb = blockIdx.x;

    const float* ag = audio + (size_t)cb * 16 * 128;
#pragma unroll
    for (int i = 0; i < 8; i++) audio_s[t + i * 256] = ag[t + i * 256];
    __syncthreads();

#pragma unroll 2
    for (int j = 0; j < 32; j++) {
        int idx = t + j * 256;
        int r = idx >> 9, h = idx & 511;
        const float4* wr = (const float4*)(W_audio + (size_t)h * 128);
        const float4* ar = (const float4*)(audio_s + r * 128);
        float s = 0.f;
#pragma unroll
        for (int kk = 0; kk < 32; kk++) {
            float4 wv = wr[kk], av = ar[kk];
            s += wv.x * av.x + wv.y * av.y + wv.z * av.z + wv.w * av.w;
        }
        s += b_audio[h];
        a_s[idx] = s > 0.f ? s : 0.f;
    }
    __syncthreads();

#pragma unroll
    for (int j = 0; j < 3; j++) {
        int idx = t + j * 256;
        int r = idx / 48, m = idx % 48;
        const float4* as4 = (const float4*)(a_s + r * 512);
        const float4* wg = (const float4*)(W_g + (size_t)m * 512);
        float s = 0.f;
#pragma unroll 8
        for (int kk = 0; kk < 128; kk++) {
            float4 a4 = as4[kk], w4 = wg[kk];
            s += a4.x * w4.x + a4.y * w4.y + a4.z * w4.z + a4.w * w4.w;
        }
        g_inter[(size_t)cb * 768 + idx] = s;
    }
}

// ---------------- probe: shifts ncu's capture window onto main_kernel ------
__global__ void probe_kernel() {}

// ---------------- kernel 3: fused main, 2 bt per CTA, 512 threads ----------------
// smem bytes:
//   vs (half, 96 x 520)            @0       99840
//   f32 A stages (2 x 96 x 64 f32) @99840   49152
//   h16 A stages (2 x 96 x 72 h)   @148992  27648
//   bvs (512 f32)                  @176640   2048
//   inter (96)  @178688 | wh (48) @179072 | zpart(192) @179264
//   red (4) @180032 | alpha (96) @180048   -> end 180432
#define OF_F32   99840
#define OF_H16   148992
#define OF_BVS   176640
#define OF_INTER 178688
#define OF_WH    179072
#define OF_ZP    179264
#define OF_RED   180032
#define OF_AL    180048
#define SMEM_BYTES 180448

__device__ __forceinline__ void issue_tile(uint32_t fbase, const float* gsrc, int t) {
    // 96 rows x 64 floats = 1536 16B chunks; gmem row stride 512 floats
#pragma unroll
    for (int i = 0; i < 3; i++) {
        int g = t + i * 512;
        int row = g >> 4, c4 = g & 15;
        cp_async16(fbase + (uint32_t)g * 16u, gsrc + (size_t)row * 512 + c4 * 4);
    }
}

__global__ __launch_bounds__(512, 1) void main_kernel(const float* __restrict__ video,
                                                      const float* __restrict__ b_video,
                                                      const float* __restrict__ W_h,
                                                      float* __restrict__ out) {
    extern __shared__ char smc[];
    uint32_t sbase = (uint32_t)__cvta_generic_to_shared(smc);
    __half* vs     = (__half*)smc;
    float* bvs     = (float*)(smc + OF_BVS);
    float* inter_s = (float*)(smc + OF_INTER);
    float* wh_s    = (float*)(smc + OF_WH);
    float* zpart   = (float*)(smc + OF_ZP);
    float* red     = (float*)(smc + OF_RED);
    float* alpha_s = (float*)(smc + OF_AL);

    int t = threadIdx.x;
    int blk = blockIdx.x;                 // bt = 2*blk, 2*blk+1
    int lane = t & 31, w = t >> 5;        // 16 warps
    int qid = lane >> 2, tq = lane & 3;

    const float* Vg = video + (size_t)blk * 96 * 512;

    // ---- phase 0: start A pipeline + small vectors ----
    issue_tile(sbase + OF_F32, Vg, t);                     CP_COMMIT();
    issue_tile(sbase + OF_F32 + 24576, Vg + KT, t);        CP_COMMIT();
    bvs[t] = b_video[t];
    if (t < 96) inter_s[t] = g_inter[(size_t)blk * 96 + t];
    if (t < 48) wh_s[t] = W_h[t];

    // ---- phase 1: v = relu(V @ W_video^T + b)  (M=96, N=512, K=512) ----
    float acc[6][4][4];
#pragma unroll
    for (int mt = 0; mt < 6; mt++)
#pragma unroll
        for (int j = 0; j < 4; j++)
#pragma unroll
            for (int r = 0; r < 4; r++) acc[mt][j][r] = 0.f;

    const uint2* Bp = g_Wvf + (size_t)(w * 4) * 32 * 32 + lane;
    uint2 bb[2][4];
#pragma unroll
    for (int j = 0; j < 4; j++) bb[0][j] = Bp[(size_t)(j * 32) * 32];

    // per-thread ldmatrix base (row = lane&15, col-seg = lane>>4)
    uint32_t lds_a = sbase + OF_H16 + (uint32_t)(((lane & 15) * STH + (lane >> 4) * 8) * 2);

    for (int tile = 0; tile < 8; ++tile) {
        int s = tile & 1;
        if (tile == 7) { CP_WAIT(0); } else { CP_WAIT(1); }
        __syncthreads();                  // f32 tile `tile` landed

        // convert f32 tile -> fp16 tile (each element once per CTA)
        {
            const float4* f4 = (const float4*)(smc + OF_F32 + s * 24576);
            __half* h16 = (__half*)(smc + OF_H16 + s * 13824);
#pragma unroll
            for (int i = 0; i < 3; i++) {
                int g = t + i * 512;
                int row = g >> 4, c4 = g & 15;
                float4 v = f4[g];
                uint32_t h0 = packh2(v.x, v.y);
                uint32_t h1 = packh2(v.z, v.w);
                *(uint2*)&h16[row * STH + c4 * 4] = make_uint2(h0, h1);
            }
        }
        __syncthreads();                  // fp16 tile visible; f32 stage free

        if (tile + 2 < 8) {
            issue_tile(sbase + OF_F32 + s * 24576, Vg + (size_t)(tile + 2) * KT, t);
            CP_COMMIT();
        }

        uint32_t abase = lds_a + (uint32_t)(s * 13824);
#pragma unroll
        for (int kk = 0; kk < 4; kk++) {
            int kg = tile * 4 + kk;       // k16 step 0..31
            int cur = kg & 1;
            if (kg < 31) {
#pragma unroll
                for (int j = 0; j < 4; j++)
                    bb[cur ^ 1][j] = Bp[(size_t)(j * 32 + kg + 1) * 32];
            }
#pragma unroll
            for (int mt = 0; mt < 6; mt++) {
                uint32_t a0, a1, a2, a3;
                ldsm_x4(a0, a1, a2, a3, abase + (uint32_t)((mt * 16 * STH + kk * 16) * 2));
#pragma unroll
                for (int j = 0; j < 4; j++)
                    mma_f16(acc[mt][j][0], acc[mt][j][1], acc[mt][j][2], acc[mt][j][3],
                            a0, a1, a2, a3, bb[cur][j].x, bb[cur][j].y);
            }
        }
    }

    // epilogue: relu(+bias), pack fp16 pairs, store v to smem
#pragma unroll
    for (int mt = 0; mt < 6; mt++) {
#pragma unroll
        for (int j = 0; j < 4; j++) {
            int r0 = mt * 16 + qid;
            int h0 = w * 32 + j * 8 + tq * 2;
            float bv0 = bvs[h0], bv1 = bvs[h0 + 1];
            float x0 = acc[mt][j][0] + bv0; x0 = x0 > 0.f ? x0 : 0.f;
            float x1 = acc[mt][j][1] + bv1; x1 = x1 > 0.f ? x1 : 0.f;
            float x2 = acc[mt][j][2] + bv0; x2 = x2 > 0.f ? x2 : 0.f;
            float x3 = acc[mt][j][3] + bv1; x3 = x3 > 0.f ? x3 : 0.f;
            *(uint32_t*)&vs[r0 * SVH + h0]       = packh2(x0, x1);
            *(uint32_t*)&vs[(r0 + 8) * SVH + h0] = packh2(x2, x3);
        }
    }
    __syncthreads();

    // ---- phase 2: content = v @ W_v^T (+inter), tanh, z partials ----
    if (w < 12) {
        int btl = w / 6, wl = w % 6;
        int mt = wl >> 1, nh = wl & 1;
        float cacc[3][4];
#pragma unroll
        for (int j = 0; j < 3; j++)
#pragma unroll
            for (int r = 0; r < 4; r++) cacc[j][r] = 0.f;

        uint32_t abase2 = sbase +
            (uint32_t)((((btl * 48 + mt * 16 + (lane & 15)) * SVH) + (lane >> 4) * 8) * 2);
#pragma unroll 4
        for (int ks = 0; ks < 32; ks++) {
            uint32_t a0, a1, a2, a3;
            ldsm_x4(a0, a1, a2, a3, abase2 + (uint32_t)(ks * 32));
#pragma unroll
            for (int j = 0; j < 3; j++) {
                uint2 b = g_Wvvf[(size_t)((nh * 3 + j) * 32 + ks) * 32 + lane];
                mma_f16(cacc[j][0], cacc[j][1], cacc[j][2], cacc[j][3],
                        a0, a1, a2, a3, b.x, b.y);
            }
        }

        int n0 = mt * 16 + qid, n1 = n0 + 8;
        float i0 = inter_s[btl * 48 + n0], i1 = inter_s[btl * 48 + n1];
        float p0 = 0.f, p1 = 0.f;
#pragma unroll
        for (int j = 0; j < 3; j++) {
            int m0i = (nh * 3 + j) * 8 + tq * 2;
            float wh0 = wh_s[m0i], wh1 = wh_s[m0i + 1];
            p0 += tanhf(cacc[j][0] + i0) * wh0 + tanhf(cacc[j][1] + i0) * wh1;
            p1 += tanhf(cacc[j][2] + i1) * wh0 + tanhf(cacc[j][3] + i1) * wh1;
        }
        p0 += __shfl_xor_sync(0xffffffffu, p0, 1);
        p0 += __shfl_xor_sync(0xffffffffu, p0, 2);
        p1 += __shfl_xor_sync(0xffffffffu, p1, 1);
        p1 += __shfl_xor_sync(0xffffffffu, p1, 2);
        if (tq == 0) {
            zpart[btl * 96 + n0 * 2 + nh] = p0;
            zpart[btl * 96 + n1 * 2 + nh] = p1;
        }
    }
    __syncthreads();

    // ---- phase 3: softmax over 48, per bt ----
    if (t < 96) {
        int btl = t / 48, n = t % 48;
        alpha_s[t] = zpart[btl * 96 + n * 2] + zpart[btl * 96 + n * 2 + 1];
    }
    __syncthreads();
    if (t == 0 || t == 256) {
        int btl = t >> 8;
        float m = -1e30f;
        for (int n = 0; n < 48; n++) m = fmaxf(m, alpha_s[btl * 48 + n]);
        red[btl * 2] = m;
    }
    __syncthreads();
    if (t < 96) alpha_s[t] = expf(alpha_s[t] - red[(t / 48) * 2]);
    __syncthreads();
    if (t == 0 || t == 256) {
        int btl = t >> 8;
        float s = 0.f;
        for (int n = 0; n < 48; n++) s += alpha_s[btl * 48 + n];
        red[btl * 2 + 1] = 1.0f / s;
    }
    __syncthreads();

    // ---- phase 4: c[k] = sum_n alpha[n] * V[n][k], exact V from global ----
    {
        int btl = t >> 8, k = t & 255;
        const float* Vrow = Vg + (size_t)btl * 48 * 512;
        float inv = red[btl * 2 + 1];
        const float* al = alpha_s + btl * 48;
        float s0 = 0.f, s1 = 0.f;
#pragma unroll 8
        for (int n = 0; n < 48; n++) {
            float a = al[n];
            s0 += a * Vrow[(size_t)n * 512 + k];
            s1 += a * Vrow[(size_t)n * 512 + k + 256];
        }
        float* ob = out + (size_t)(blk * 2 + btl) * 512;
        ob[k] = s0 * inv;
        ob[k + 256] = s1 * inv;
    }
}

// ---------------- launch ----------------
extern "C" void kernel_launch(void* const* d_in, const int* in_sizes, int n_in,
                              void* d_out, int out_size) {
    const float* audio   = (const float*)d_in[0];
    const float* video   = (const float*)d_in[1];
    const float* W_audio = (const float*)d_in[2];
    const float* b_audio = (const float*)d_in[3];
    const float* W_video = (const float*)d_in[4];
    const float* b_video = (const float*)d_in[5];
    const float* W_v     = (const float*)d_in[6];
    const float* W_g     = (const float*)d_in[7];
    const float* W_h     = (const float*)d_in[8];
    float* out = (float*)d_out;

    (void)in_sizes; (void)n_in; (void)out_size;

    cudaFuncSetAttribute(main_kernel, cudaFuncAttributeMaxDynamicSharedMemorySize, SMEM_BYTES);

    prep_kernel<<<280, 256>>>(W_video, W_v);
    audio_kernel<<<BT_TOTAL / 16, 256>>>(audio, W_audio, b_audio, W_g);
    probe_kernel<<<1, 32>>>();   // shifts ncu -s5 capture window onto main_kernel
    main_kernel<<<BT_TOTAL / 2, 512, SMEM_BYTES>>>(video, b_video, W_h, out);
}

// round 8
// speedup vs baseline: 1.7829x; 1.0614x over previous
#include <cuda_runtime.h>
#include <cuda_fp16.h>
#include <cstdint>
#include <cstddef>

// B=32, T=64 -> BT=2048. audio [BT,128], video [BT,48,512], W_audio[512,128],
// b_audio[512], W_video[512,512], b_video[512], W_v[48,512], W_g[48,512], W_h[1,48]
#define BT_TOTAL 2048
#define SVH 520               // vs row stride (halfs); 1040B -> LDSM conflict-free
#define KT 64                 // A k-tile (8 tiles over K=512)
#define STH 72                // fp16 tile row stride (halfs); 144B -> LDSM conflict-free

// ---------------- device scratch ----------------
__device__ uint2 g_Wvf[64 * 32 * 32];   // W_video fp16 B-frags: [h8][k16][lane] (512KB)
__device__ uint2 g_Wvvf[6 * 32 * 32];   // W_v     fp16 B-frags: [m8][k16][lane] (48KB)
__device__ float g_inter[BT_TOTAL * 48];

// ---------------- helpers ----------------
__device__ __forceinline__ uint32_t packh2(float lo, float hi) {
    __half2 h = __floats2half2_rn(lo, hi);
    return *(uint32_t*)&h;
}

__device__ __forceinline__ void mma_f16(float& d0, float& d1, float& d2, float& d3,
                                        uint32_t a0, uint32_t a1, uint32_t a2, uint32_t a3,
                                        uint32_t b0, uint32_t b1) {
    asm volatile(
        "mma.sync.aligned.m16n8k16.row.col.f32.f16.f16.f32 "
        "{%0,%1,%2,%3}, {%4,%5,%6,%7}, {%8,%9}, {%0,%1,%2,%3};\n"
        : "+f"(d0), "+f"(d1), "+f"(d2), "+f"(d3)
        : "r"(a0), "r"(a1), "r"(a2), "r"(a3), "r"(b0), "r"(b1));
}

__device__ __forceinline__ void ldsm_x4(uint32_t& a0, uint32_t& a1, uint32_t& a2, uint32_t& a3,
                                        uint32_t saddr) {
    asm volatile("ldmatrix.sync.aligned.m8n8.x4.shared.b16 {%0,%1,%2,%3}, [%4];"
                 : "=r"(a0), "=r"(a1), "=r"(a2), "=r"(a3) : "r"(saddr));
}

__device__ __forceinline__ void cp_async16(uint32_t saddr, const float* gaddr) {
    asm volatile("cp.async.ca.shared.global [%0], [%1], 16;" :: "r"(saddr), "l"(gaddr));
}
#define CP_COMMIT() asm volatile("cp.async.commit_group;")
#define CP_WAIT(n)  asm volatile("cp.async.wait_group %0;" :: "n"(n))

// ---------------- kernel 1: fp16 frag-ordered weights ----------------
__global__ void prep_kernel(const float* __restrict__ Wvid, const float* __restrict__ Wv) {
    int idx = blockIdx.x * 256 + threadIdx.x;
    if (idx < 64 * 32 * 32) {
        int lane = idx & 31, tile = idx >> 5;
        int h8 = tile >> 5, ks = tile & 31;
        int row = h8 * 8 + (lane >> 2);
        int col = ks * 16 + (lane & 3) * 2;
        const float* W = Wvid + (size_t)row * 512 + col;
        g_Wvf[idx] = make_uint2(packh2(W[0], W[1]), packh2(W[8], W[9]));
    } else {
        int j = idx - 64 * 32 * 32;
        if (j < 6 * 32 * 32) {
            int lane = j & 31, tile = j >> 5;
            int m8 = tile >> 5, ks = tile & 31;
            int row = m8 * 8 + (lane >> 2);
            int col = ks * 16 + (lane & 3) * 2;
            const float* W = Wv + (size_t)row * 512 + col;
            g_Wvvf[j] = make_uint2(packh2(W[0], W[1]), packh2(W[8], W[9]));
        }
    }
}

// ---------------- kernel 2: audio path -> inter[bt][48] ----------------
// Each thread owns 2 h-rows; W_audio row read ONCE; all 16 r accumulated in
// registers (audio_s reads are warp-uniform -> smem broadcast).
__global__ __launch_bounds__(256) void audio_kernel(const float* __restrict__ audio,
                                                    const float* __restrict__ W_audio,
                                                    const float* __restrict__ b_audio,
                                                    const float* __restrict__ W_g) {
    __shared__ float audio_s[16 * 128];
    __shared__ float a_s[16 * 512];
    int t = threadIdx.x;
    int cb = blockIdx.x;

    const float* ag = audio + (size_t)cb * 16 * 128;
#pragma unroll
    for (int i = 0; i < 8; i++) audio_s[t + i * 256] = ag[t + i * 256];
    __syncthreads();

    const float4* as4 = (const float4*)audio_s;   // [16][32]
#pragma unroll
    for (int half = 0; half < 2; half++) {
        int h = t + half * 256;
        const float4* wr = (const float4*)(W_audio + (size_t)h * 128);
        float acc[16];
#pragma unroll
        for (int r = 0; r < 16; r++) acc[r] = 0.f;
#pragma unroll 4
        for (int kk = 0; kk < 32; kk++) {
            float4 wv = wr[kk];
#pragma unroll
            for (int r = 0; r < 16; r++) {
                float4 av = as4[r * 32 + kk];
                acc[r] += wv.x * av.x + wv.y * av.y + wv.z * av.z + wv.w * av.w;
            }
        }
        float bb = b_audio[h];
#pragma unroll
        for (int r = 0; r < 16; r++) {
            float s = acc[r] + bb;
            a_s[r * 512 + h] = s > 0.f ? s : 0.f;
        }
    }
    __syncthreads();

    // inter[r][m] = a[r] . W_g[m]   (W_g is 98KB -> L1-resident)
#pragma unroll
    for (int j = 0; j < 3; j++) {
        int idx = t + j * 256;
        int r = idx / 48, m = idx % 48;
        const float4* ar = (const float4*)(a_s + r * 512);
        const float4* wg = (const float4*)(W_g + (size_t)m * 512);
        float s = 0.f;
#pragma unroll 8
        for (int kk = 0; kk < 128; kk++) {
            float4 a4 = ar[kk], w4 = wg[kk];
            s += a4.x * w4.x + a4.y * w4.y + a4.z * w4.z + a4.w * w4.w;
        }
        g_inter[(size_t)cb * 768 + idx] = s;
    }
}

// ---------------- probe: keeps ncu capture window on main_kernel ------
__global__ void probe_kernel() {}

// ---------------- kernel 3: fused main, 2 bt per CTA, 512 threads ----------------
#define OF_F32   99840
#define OF_H16   148992
#define OF_BVS   176640
#define OF_INTER 178688
#define OF_WH    179072
#define OF_ZP    179264
#define OF_RED   180032
#define OF_AL    180048
#define SMEM_BYTES 180448

__device__ __forceinline__ void issue_tile(uint32_t fbase, const float* gsrc, int t) {
    // 96 rows x 64 floats = 1536 16B chunks; gmem row stride 512 floats
#pragma unroll
    for (int i = 0; i < 3; i++) {
        int g = t + i * 512;
        int row = g >> 4, c4 = g & 15;
        cp_async16(fbase + (uint32_t)g * 16u, gsrc + (size_t)row * 512 + c4 * 4);
    }
}

// convert f32 stage s -> h16 stage s. Thread t converts EXACTLY the chunks it
// cp.async'd in issue_tile (same g mapping) -> cp.async.wait_group alone
// orders this; no barrier needed between landing and convert.
__device__ __forceinline__ void convert_tile(char* smc, int s, int t) {
    const float4* f4 = (const float4*)(smc + OF_F32 + s * 24576);
    __half* h16 = (__half*)(smc + OF_H16 + s * 13824);
#pragma unroll
    for (int i = 0; i < 3; i++) {
        int g = t + i * 512;
        int row = g >> 4, c4 = g & 15;
        float4 v = f4[g];
        *(uint2*)&h16[row * STH + c4 * 4] = make_uint2(packh2(v.x, v.y), packh2(v.z, v.w));
    }
}

__global__ __launch_bounds__(512, 1) void main_kernel(const float* __restrict__ video,
                                                      const float* __restrict__ b_video,
                                                      const float* __restrict__ W_h,
                                                      float* __restrict__ out) {
    extern __shared__ char smc[];
    uint32_t sbase = (uint32_t)__cvta_generic_to_shared(smc);
    __half* vs     = (__half*)smc;
    float* bvs     = (float*)(smc + OF_BVS);
    float* inter_s = (float*)(smc + OF_INTER);
    float* wh_s    = (float*)(smc + OF_WH);
    float* zpart   = (float*)(smc + OF_ZP);
    float* red     = (float*)(smc + OF_RED);
    float* alpha_s = (float*)(smc + OF_AL);

    int t = threadIdx.x;
    int blk = blockIdx.x;                 // bt = 2*blk, 2*blk+1
    int lane = t & 31, w = t >> 5;        // 16 warps
    int qid = lane >> 2, tq = lane & 3;

    const float* Vg = video + (size_t)blk * 96 * 512;

    // ---- phase 0: pipeline prologue ----
    issue_tile(sbase + OF_F32, Vg, t);                  CP_COMMIT();   // t0
    issue_tile(sbase + OF_F32 + 24576, Vg + KT, t);     CP_COMMIT();   // t1
    bvs[t] = b_video[t];
    if (t < 96) inter_s[t] = g_inter[(size_t)blk * 96 + t];
    if (t < 48) wh_s[t] = W_h[t];

    float acc[6][4][4];
#pragma unroll
    for (int mt = 0; mt < 6; mt++)
#pragma unroll
        for (int j = 0; j < 4; j++)
#pragma unroll
            for (int r = 0; r < 4; r++) acc[mt][j][r] = 0.f;

    const uint2* Bp = g_Wvf + (size_t)(w * 4) * 32 * 32 + lane;
    uint2 bb[2][4];
#pragma unroll
    for (int j = 0; j < 4; j++) bb[0][j] = Bp[(size_t)(j * 32) * 32];

    uint32_t lds_a = sbase + OF_H16 + (uint32_t)(((lane & 15) * STH + (lane >> 4) * 8) * 2);

    CP_WAIT(1);                    // t0 landed (own chunks)
    convert_tile(smc, 0, t);       // h16[0] <- t0
    __syncthreads();               // h16[0] + bvs/inter visible to all

    // ---- phase 1: v = relu(V @ W_video^T + b)  (M=96, N=512, K=512) ----
    // One barrier per tile: convert(tile+1) overlaps mma(tile).
    for (int tile = 0; tile < 8; ++tile) {
        int s = tile & 1;
        if (tile + 2 < 8) {        // f32[s] freed by convert(tile) last iter
            issue_tile(sbase + OF_F32 + s * 24576, Vg + (size_t)(tile + 2) * KT, t);
            CP_COMMIT();
        }
        if (tile + 1 < 8) {
            if (tile + 2 < 8) { CP_WAIT(1); } else { CP_WAIT(0); }
            convert_tile(smc, s ^ 1, t);   // h16[s^1] <- tile+1 (own chunks only)
        }

        uint32_t abase = lds_a + (uint32_t)(s * 13824);
#pragma unroll
        for (int kk = 0; kk < 4; kk++) {
            int kg = tile * 4 + kk;        // k16 step 0..31
            int cur = kg & 1;
            if (kg < 31) {
#pragma unroll
                for (int j = 0; j < 4; j++)
                    bb[cur ^ 1][j] = Bp[(size_t)(j * 32 + kg + 1) * 32];
            }
#pragma unroll
            for (int mt = 0; mt < 6; mt++) {
                uint32_t a0, a1, a2, a3;
                ldsm_x4(a0, a1, a2, a3, abase + (uint32_t)((mt * 16 * STH + kk * 16) * 2));
#pragma unroll
                for (int j = 0; j < 4; j++)
                    mma_f16(acc[mt][j][0], acc[mt][j][1], acc[mt][j][2], acc[mt][j][3],
                            a0, a1, a2, a3, bb[cur][j].x, bb[cur][j].y);
            }
        }
        __syncthreads();   // mma(tile) reads done; h16[s^1] visible for next iter
    }

    // epilogue: relu(+bias), pack fp16 pairs, store v to smem
#pragma unroll
    for (int mt = 0; mt < 6; mt++) {
#pragma unroll
        for (int j = 0; j < 4; j++) {
            int r0 = mt * 16 + qid;
            int h0 = w * 32 + j * 8 + tq * 2;
            float bv0 = bvs[h0], bv1 = bvs[h0 + 1];
            float x0 = acc[mt][j][0] + bv0; x0 = x0 > 0.f ? x0 : 0.f;
            float x1 = acc[mt][j][1] + bv1; x1 = x1 > 0.f ? x1 : 0.f;
            float x2 = acc[mt][j][2] + bv0; x2 = x2 > 0.f ? x2 : 0.f;
            float x3 = acc[mt][j][3] + bv1; x3 = x3 > 0.f ? x3 : 0.f;
            *(uint32_t*)&vs[r0 * SVH + h0]       = packh2(x0, x1);
            *(uint32_t*)&vs[(r0 + 8) * SVH + h0] = packh2(x2, x3);
        }
    }
    __syncthreads();

    // ---- phase 2: content = v @ W_v^T (+inter), tanh, z partials ----
    if (w < 12) {
        int btl = w / 6, wl = w % 6;
        int mt = wl >> 1, nh = wl & 1;
        float cacc[3][4];
#pragma unroll
        for (int j = 0; j < 3; j++)
#pragma unroll
            for (int r = 0; r < 4; r++) cacc[j][r] = 0.f;

        const uint2* Bp2 = g_Wvvf + (size_t)(nh * 3) * 32 * 32 + lane;
        uint2 bb2[2][3];
#pragma unroll
        for (int j = 0; j < 3; j++) bb2[0][j] = Bp2[(size_t)(j * 32) * 32];

        uint32_t abase2 = sbase +
            (uint32_t)((((btl * 48 + mt * 16 + (lane & 15)) * SVH) + (lane >> 4) * 8) * 2);
#pragma unroll 4
        for (int ks = 0; ks < 32; ks++) {
            int cur = ks & 1;
            if (ks < 31) {
#pragma unroll
                for (int j = 0; j < 3; j++)
                    bb2[cur ^ 1][j] = Bp2[(size_t)(j * 32 + ks + 1) * 32];
            }
            uint32_t a0, a1, a2, a3;
            ldsm_x4(a0, a1, a2, a3, abase2 + (uint32_t)(ks * 32));
#pragma unroll
            for (int j = 0; j < 3; j++)
                mma_f16(cacc[j][0], cacc[j][1], cacc[j][2], cacc[j][3],
                        a0, a1, a2, a3, bb2[cur][j].x, bb2[cur][j].y);
        }

        int n0 = mt * 16 + qid, n1 = n0 + 8;
        float i0 = inter_s[btl * 48 + n0], i1 = inter_s[btl * 48 + n1];
        float p0 = 0.f, p1 = 0.f;
#pragma unroll
        for (int j = 0; j < 3; j++) {
            int m0i = (nh * 3 + j) * 8 + tq * 2;
            float wh0 = wh_s[m0i], wh1 = wh_s[m0i + 1];
            p0 += tanhf(cacc[j][0] + i0) * wh0 + tanhf(cacc[j][1] + i0) * wh1;
            p1 += tanhf(cacc[j][2] + i1) * wh0 + tanhf(cacc[j][3] + i1) * wh1;
        }
        p0 += __shfl_xor_sync(0xffffffffu, p0, 1);
        p0 += __shfl_xor_sync(0xffffffffu, p0, 2);
        p1 += __shfl_xor_sync(0xffffffffu, p1, 1);
        p1 += __shfl_xor_sync(0xffffffffu, p1, 2);
        if (tq == 0) {
            zpart[btl * 96 + n0 * 2 + nh] = p0;
            zpart[btl * 96 + n1 * 2 + nh] = p1;
        }
    }
    __syncthreads();

    // ---- phase 3: softmax over 48, per bt ----
    if (t < 96) {
        int btl = t / 48, n = t % 48;
        alpha_s[t] = zpart[btl * 96 + n * 2] + zpart[btl * 96 + n * 2 + 1];
    }
    __syncthreads();
    if (t == 0 || t == 256) {
        int btl = t >> 8;
        float m = -1e30f;
        for (int n = 0; n < 48; n++) m = fmaxf(m, alpha_s[btl * 48 + n]);
        red[btl * 2] = m;
    }
    __syncthreads();
    if (t < 96) alpha_s[t] = expf(alpha_s[t] - red[(t / 48) * 2]);
    __syncthreads();
    if (t == 0 || t == 256) {
        int btl = t >> 8;
        float s = 0.f;
        for (int n = 0; n < 48; n++) s += alpha_s[btl * 48 + n];
        red[btl * 2 + 1] = 1.0f / s;
    }
    __syncthreads();

    // ---- phase 4: c[k] = sum_n alpha[n] * V[n][k], exact V from global ----
    {
        int btl = t >> 8, k = t & 255;
        const float* Vrow = Vg + (size_t)btl * 48 * 512;
        float inv = red[btl * 2 + 1];
        const float* al = alpha_s + btl * 48;
        float s0 = 0.f, s1 = 0.f;
#pragma unroll 8
        for (int n = 0; n < 48; n++) {
            float a = al[n];
            s0 += a * Vrow[(size_t)n * 512 + k];
            s1 += a * Vrow[(size_t)n * 512 + k + 256];
        }
        float* ob = out + (size_t)(blk * 2 + btl) * 512;
        ob[k] = s0 * inv;
        ob[k + 256] = s1 * inv;
    }
}

// ---------------- launch ----------------
extern "C" void kernel_launch(void* const* d_in, const int* in_sizes, int n_in,
                              void* d_out, int out_size) {
    const float* audio   = (const float*)d_in[0];
    const float* video   = (const float*)d_in[1];
    const float* W_audio = (const float*)d_in[2];
    const float* b_audio = (const float*)d_in[3];
    const float* W_video = (const float*)d_in[4];
    const float* b_video = (const float*)d_in[5];
    const float* W_v     = (const float*)d_in[6];
    const float* W_g     = (const float*)d_in[7];
    const float* W_h     = (const float*)d_in[8];
    float* out = (float*)d_out;

    (void)in_sizes; (void)n_in; (void)out_size;

    cudaFuncSetAttribute(main_kernel, cudaFuncAttributeMaxDynamicSharedMemorySize, SMEM_BYTES);

    prep_kernel<<<280, 256>>>(W_video, W_v);
    audio_kernel<<<BT_TOTAL / 16, 256>>>(audio, W_audio, b_audio, W_g);
    probe_kernel<<<1, 32>>>();   // keeps ncu -s5 capture window on main_kernel
    main_kernel<<<BT_TOTAL / 2, 512, SMEM_BYTES>>>(video, b_video, W_h, out);
}